// round 5
// baseline (speedup 1.0000x reference)
#include <cuda_runtime.h>
#include <cuda_bf16.h>

// Problem constants (match reference)
#define NXg 2048
#define NYg 2048

#define ROWS_PER_THREAD 4
#define TPB 256
#define GRID_X (NYg / 4 / TPB)            // 2
#define GRID_Y (NXg / ROWS_PER_THREAD)    // 512
#define NBLOCKS (GRID_X * GRID_Y)         // 1024

// Final scale: diffs accumulated unscaled (one-sided doubled, exact since
// INV_H = 2*INV_2H and both are powers of two). energy = 0.5 * acc * INV_2H^2.
#define FINAL_SCALE (0.5f * 1024.0f * 1024.0f)

// Self-resetting cross-block accumulator (no separate zeroing kernel).
__device__ float    g_scratch = 0.0f;
__device__ unsigned g_count   = 0u;

__global__ __launch_bounds__(TPB)
void flow_energy_kernel(const float* __restrict__ phi, float* __restrict__ out) {
    const int quad = blockIdx.x * TPB + threadIdx.x;   // column quad index (0..511)
    const int j0   = quad * 4;                          // first column of this quad
    const int r0   = blockIdx.y * ROWS_PER_THREAD;      // first row of this tile
    const int qstride = NYg / 4;

    const float4* __restrict__ phi4 = reinterpret_cast<const float4*>(phi);

    // Front-batched loads: rows r0-1 .. r0+ROWS (row-clamped; clamped rows are
    // only consumed by one-sided branches where they drop out).
    float4 v[ROWS_PER_THREAD + 2];
    #pragma unroll
    for (int i = 0; i < ROWS_PER_THREAD + 2; i++) {
        int r = r0 - 1 + i;
        r = (r < 0) ? 0 : ((r > NXg - 1) ? NXg - 1 : r);
        v[i] = phi4[r * qstride + quad];
    }

    const int  lane       = threadIdx.x & 31;
    const bool left_edge  = (j0 == 0);
    const bool right_edge = (j0 + 4 == NYg);

    float acc = 0.0f;

    #pragma unroll
    for (int rr = 0; rr < ROWS_PER_THREAD; rr++) {
        const int r = r0 + rr;
        const float4 prev = v[rr];
        const float4 cur  = v[rr + 1];
        const float4 next = v[rr + 2];

        // ---- vx (row-direction diff), unscaled; one-sided doubled ----
        float dx0, dx1, dx2, dx3;
        if (r == 0) {
            dx0 = 2.0f * (next.x - cur.x);
            dx1 = 2.0f * (next.y - cur.y);
            dx2 = 2.0f * (next.z - cur.z);
            dx3 = 2.0f * (next.w - cur.w);
        } else if (r == NXg - 1) {
            dx0 = 2.0f * (cur.x - prev.x);
            dx1 = 2.0f * (cur.y - prev.y);
            dx2 = 2.0f * (cur.z - prev.z);
            dx3 = 2.0f * (cur.w - prev.w);
        } else {
            dx0 = next.x - prev.x;
            dx1 = next.y - prev.y;
            dx2 = next.z - prev.z;
            dx3 = next.w - prev.w;
        }

        // ---- vy (column-direction diff) ----
        float l  = __shfl_up_sync(0xFFFFFFFFu, cur.w, 1);
        float rt = __shfl_down_sync(0xFFFFFFFFu, cur.x, 1);
        if (lane == 0 && !left_edge)
            l = __ldg(&phi[r * NYg + j0 - 1]);
        if (lane == 31 && !right_edge)
            rt = __ldg(&phi[r * NYg + j0 + 4]);

        float dy0 = left_edge  ? 2.0f * (cur.y - cur.x) : (cur.y - l);
        float dy1 = cur.z - cur.x;
        float dy2 = cur.w - cur.y;
        float dy3 = right_edge ? 2.0f * (cur.w - cur.z) : (rt - cur.z);

        acc = fmaf(dx0, dx0, acc); acc = fmaf(dx1, dx1, acc);
        acc = fmaf(dx2, dx2, acc); acc = fmaf(dx3, dx3, acc);
        acc = fmaf(dy0, dy0, acc); acc = fmaf(dy1, dy1, acc);
        acc = fmaf(dy2, dy2, acc); acc = fmaf(dy3, dy3, acc);
    }

    // ---- warp reduce ----
    #pragma unroll
    for (int o = 16; o > 0; o >>= 1)
        acc += __shfl_xor_sync(0xFFFFFFFFu, acc, o);

    // ---- block reduce ----
    __shared__ float warp_sums[TPB / 32];
    const int wid = threadIdx.x >> 5;
    if (lane == 0) warp_sums[wid] = acc;
    __syncthreads();

    if (threadIdx.x == 0) {
        float s = warp_sums[0];
        #pragma unroll
        for (int w = 1; w < TPB / 32; w++) s += warp_sums[w];

        // Cross-block accumulation with self-reset (single-kernel graph).
        atomicAdd(&g_scratch, s * FINAL_SCALE);
        __threadfence();
        unsigned ticket = atomicAdd(&g_count, 1u);
        if (ticket == NBLOCKS - 1) {
            // All other blocks' adds are visible (fence before their count inc).
            float tot = *((volatile float*)&g_scratch);
            out[0]    = tot;
            g_scratch = 0.0f;   // reset for next graph replay
            g_count   = 0u;
            __threadfence();
        }
    }
}

extern "C" void kernel_launch(void* const* d_in, const int* in_sizes, int n_in,
                              void* d_out, int out_size) {
    // d_in[0] = pos (unused), d_in[1] = potential_field [2048*2048] fp32
    const float* phi = (const float*)d_in[1];
    float* out = (float*)d_out;

    dim3 grid(GRID_X, GRID_Y);
    flow_energy_kernel<<<grid, TPB>>>(phi, out);
}